// round 14
// baseline (speedup 1.0000x reference)
#include <cuda_runtime.h>
#include <cuda_bf16.h>
#include <cstdint>

// Shapes (fixed by dataset):
//   messages (B=32, E=8192, D=128) fp32 | tgt (B=32, E=8192) int32
//   out      (B=32, N=2048, D=128) fp32
static constexpr int B = 32;
static constexpr int E = 8192;
static constexpr int N = 2048;
static constexpr int D = 128;               // 32 float4 per row
static constexpr int ROWS = 8;              // 4 pre-wait loads + 4 post (prefetched)
static constexpr int WARPS = 8;             // warps per block
static constexpr int OUT_F4 = B * N * D / 4;   // 2097152 float4

// ── Primary: zero the output. PDL trigger at entry; 2x-unrolled STG.128.
__global__ __launch_bounds__(256) void zero_out(float4* __restrict__ out4)
{
    asm volatile("griddepcontrol.launch_dependents;" ::: "memory");
    const float4 z = make_float4(0.f, 0.f, 0.f, 0.f);
    const int stride = gridDim.x * 512;
    int i = blockIdx.x * 512 + threadIdx.x;
    for (; i + 256 < OUT_F4; i += stride) {
        out4[i]       = z;
        out4[i + 256] = z;
    }
    if (i < OUT_F4) out4[i] = z;
}

// ── Secondary (PDL):
//   pre-wait : 4 row loads held in registers + register-free L2 prefetch of
//              the other 4 rows (covers the zero window at low reg cost)
//   post-wait: load prefetched rows (L2 hits), scatter both batches
__global__ __launch_bounds__(WARPS * 32) void scatter_add(
    const float4* __restrict__ messages,   // (B*E, 32) float4
    const int*    __restrict__ tgt,        // (B*E,)
    float*        __restrict__ out)        // (B*N*D,)
{
    const int warp = blockIdx.x * WARPS + (threadIdx.x >> 5);
    const int lane = threadIdx.x & 31;
    const int row0 = warp * ROWS;

    // Index fetch: lanes 0..3 load int2 pairs (one 32B sector).
    int t = 0, t2 = 0;
    if (lane < ROWS / 2) {
        const int2 p = __ldg((const int2*)&tgt[row0 + lane * 2]);
        t  = p.x;
        t2 = p.y;
    }

    // Pre-wait batch: rows 0..3 into registers.
    float4 v[4];
#pragma unroll
    for (int r = 0; r < 4; r++)
        v[r] = __ldcs(&messages[(size_t)(row0 + r) * 32 + lane]);

    // Register-free L2 prefetch of rows 4..7 (one line per lane per row).
#pragma unroll
    for (int r = 4; r < 8; r++)
        asm volatile("prefetch.global.L2 [%0];"
                     :: "l"(&messages[(size_t)(row0 + r) * 32 + lane]));

    asm volatile("griddepcontrol.wait;" ::: "memory");

    // Post-wait: rows 4..7 (L2 hits thanks to the prefetch), issued before
    // scattering rows 0..3 so any residual latency hides under RED issue.
    float4 w[4];
#pragma unroll
    for (int r = 0; r < 4; r++)
        w[r] = __ldcs(&messages[(size_t)(row0 + 4 + r) * 32 + lane]);

#pragma unroll
    for (int r = 0; r < 4; r++) {
        const int src = r >> 1;
        const int tr  = (r & 1) ? __shfl_sync(0xFFFFFFFFu, t2, src)
                                : __shfl_sync(0xFFFFFFFFu, t,  src);
        const int b   = (row0 + r) >> 13;
        float* dst = out + ((size_t)(b * N + tr) * D) + lane * 4;
        asm volatile(
            "red.global.add.v4.f32 [%0], {%1, %2, %3, %4};"
            :: "l"(dst), "f"(v[r].x), "f"(v[r].y), "f"(v[r].z), "f"(v[r].w)
            : "memory");
    }
#pragma unroll
    for (int r = 4; r < 8; r++) {
        const int src = r >> 1;
        const int tr  = (r & 1) ? __shfl_sync(0xFFFFFFFFu, t2, src)
                                : __shfl_sync(0xFFFFFFFFu, t,  src);
        const int b   = (row0 + r) >> 13;
        float* dst = out + ((size_t)(b * N + tr) * D) + lane * 4;
        asm volatile(
            "red.global.add.v4.f32 [%0], {%1, %2, %3, %4};"
            :: "l"(dst), "f"(w[r - 4].x), "f"(w[r - 4].y),
               "f"(w[r - 4].z), "f"(w[r - 4].w)
            : "memory");
    }
}

extern "C" void kernel_launch(void* const* d_in, const int* in_sizes, int n_in,
                              void* d_out, int out_size)
{
    const float4* messages = (const float4*)d_in[0];
    const int*    tgt      = (const int*)d_in[1];

    // Primary: zero kernel (wider grid -> shorter exposed tail under PDL).
    zero_out<<<2368, 256>>>((float4*)d_out);

    // Secondary: scatter with programmatic dependent launch.
    cudaLaunchConfig_t cfg = {};
    const int total_rows = B * E;                       // 262144
    cfg.gridDim  = dim3(total_rows / (WARPS * ROWS));   // 4096
    cfg.blockDim = dim3(WARPS * 32);
    cfg.dynamicSmemBytes = 0;
    cfg.stream = 0;
    cudaLaunchAttribute attr[1];
    attr[0].id = cudaLaunchAttributeProgrammaticStreamSerialization;
    attr[0].val.programmaticStreamSerializationAllowed = 1;
    cfg.attrs = attr;
    cfg.numAttrs = 1;
    cudaLaunchKernelEx(&cfg, scatter_add, messages, tgt, (float*)d_out);
}

// round 15
// speedup vs baseline: 1.0624x; 1.0624x over previous
#include <cuda_runtime.h>
#include <cuda_bf16.h>
#include <cstdint>

// Shapes (fixed by dataset):
//   messages (B=32, E=8192, D=128) fp32 | tgt (B=32, E=8192) int32
//   out      (B=32, N=2048, D=128) fp32
static constexpr int B = 32;
static constexpr int E = 8192;
static constexpr int N = 2048;
static constexpr int D = 128;               // 32 float4 per row
static constexpr int ROWS = 8;              // rows per warp (4 pre-wait + 4 post)
static constexpr int WARPS = 8;             // warps per block
static constexpr int OUT_F4 = B * N * D / 4;   // 2097152 float4

// ── Primary: zero the output. PDL trigger at entry; 2x-unrolled STG.128.
__global__ __launch_bounds__(256) void zero_out(float4* __restrict__ out4)
{
    asm volatile("griddepcontrol.launch_dependents;" ::: "memory");
    const float4 z = make_float4(0.f, 0.f, 0.f, 0.f);
    const int stride = gridDim.x * 512;
    int i = blockIdx.x * 512 + threadIdx.x;
    for (; i + 256 < OUT_F4; i += stride) {
        out4[i]       = z;
        out4[i + 256] = z;
    }
    if (i < OUT_F4) out4[i] = z;
}

// ── Secondary (PDL): rows 0..3 load pre-wait (covers the zero window with
//    only 4 live float4). Rows 4..7 load post-wait, issued BEFORE scattering
//    rows 0..3 so their latency hides under the first batch's RED issue.
__global__ __launch_bounds__(WARPS * 32) void scatter_add(
    const float4* __restrict__ messages,   // (B*E, 32) float4
    const int*    __restrict__ tgt,        // (B*E,)
    float*        __restrict__ out)        // (B*N*D,)
{
    const int warp = blockIdx.x * WARPS + (threadIdx.x >> 5);
    const int lane = threadIdx.x & 31;
    const int row0 = warp * ROWS;

    // Index fetch: lanes 0..3 load int2 pairs (one 32B sector).
    int t = 0, t2 = 0;
    if (lane < ROWS / 2) {
        const int2 p = __ldg((const int2*)&tgt[row0 + lane * 2]);
        t  = p.x;
        t2 = p.y;
    }

    // Pre-wait batch: rows 0..3.
    float4 v[4];
#pragma unroll
    for (int r = 0; r < 4; r++)
        v[r] = __ldcs(&messages[(size_t)(row0 + r) * 32 + lane]);

    asm volatile("griddepcontrol.wait;" ::: "memory");

    // Post-wait: issue loads for rows 4..7 first (latency hidden under the
    // RED issue of rows 0..3), then scatter both batches.
    float4 w[4];
#pragma unroll
    for (int r = 0; r < 4; r++)
        w[r] = __ldcs(&messages[(size_t)(row0 + 4 + r) * 32 + lane]);

#pragma unroll
    for (int r = 0; r < 4; r++) {
        const int src = r >> 1;
        const int tr  = (r & 1) ? __shfl_sync(0xFFFFFFFFu, t2, src)
                                : __shfl_sync(0xFFFFFFFFu, t,  src);
        const int b   = (row0 + r) >> 13;
        float* dst = out + ((size_t)(b * N + tr) * D) + lane * 4;
        asm volatile(
            "red.global.add.v4.f32 [%0], {%1, %2, %3, %4};"
            :: "l"(dst), "f"(v[r].x), "f"(v[r].y), "f"(v[r].z), "f"(v[r].w)
            : "memory");
    }
#pragma unroll
    for (int r = 4; r < 8; r++) {
        const int src = r >> 1;
        const int tr  = (r & 1) ? __shfl_sync(0xFFFFFFFFu, t2, src)
                                : __shfl_sync(0xFFFFFFFFu, t,  src);
        const int b   = (row0 + r) >> 13;
        float* dst = out + ((size_t)(b * N + tr) * D) + lane * 4;
        asm volatile(
            "red.global.add.v4.f32 [%0], {%1, %2, %3, %4};"
            :: "l"(dst), "f"(w[r - 4].x), "f"(w[r - 4].y),
               "f"(w[r - 4].z), "f"(w[r - 4].w)
            : "memory");
    }
}

extern "C" void kernel_launch(void* const* d_in, const int* in_sizes, int n_in,
                              void* d_out, int out_size)
{
    const float4* messages = (const float4*)d_in[0];
    const int*    tgt      = (const int*)d_in[1];

    // Primary: zero kernel (wide grid to minimize its tail).
    zero_out<<<1184, 256>>>((float4*)d_out);

    // Secondary: scatter with programmatic dependent launch.
    cudaLaunchConfig_t cfg = {};
    const int total_rows = B * E;                       // 262144
    cfg.gridDim  = dim3(total_rows / (WARPS * ROWS));   // 4096
    cfg.blockDim = dim3(WARPS * 32);
    cfg.dynamicSmemBytes = 0;
    cfg.stream = 0;
    cudaLaunchAttribute attr[1];
    attr[0].id = cudaLaunchAttributeProgrammaticStreamSerialization;
    attr[0].val.programmaticStreamSerializationAllowed = 1;
    cfg.attrs = attr;
    cfg.numAttrs = 1;
    cudaLaunchKernelEx(&cfg, scatter_add, messages, tgt, (float*)d_out);
}